// round 7
// baseline (speedup 1.0000x reference)
#include <cuda_runtime.h>
#include <cstdint>

#define B_  512
#define C_  6
#define T_  77
#define D_  512
#define LI_ 193

#define OFF_GT 0
#define OFF_GI (B_ * D_)
#define OFF_LT (2 * B_ * D_)
#define OFF_LS (2 * B_ * D_ + B_ * C_ * D_)

#define T_SPLIT 39   // T-half 0: [0,39), T-half 1: [39,77)

// Grid = B * 2: CTA (b, h) handles d-range [h*256, (h+1)*256).
// Block 128 = 2 T-halves x 64 float4 columns. Each thread accumulates all 6
// channels over its ~38 timesteps; partials combine via smem.
__global__ __launch_bounds__(128, 8)
void clip_fused_kernel(const float* __restrict__ image_features,   // [B, LI, D]
                       const float* __restrict__ text_features,    // [B, T, D]
                       const float* __restrict__ logit_scale,      // [1]
                       const int*   __restrict__ captions,         // [B, T]
                       const int*   __restrict__ noun_chunk_mask,  // [B, C, T]
                       float* __restrict__ out)
{
    const int b     = blockIdx.x >> 1;
    const int h     = blockIdx.x & 1;       // which D-half
    const int tid   = threadIdx.x;
    const int thalf = tid >> 6;             // 0 or 1 (T-half)
    const int col   = tid & 63;             // float4 col within D-half

    __shared__ int    s_mask[T_];           // bit c set if mask[b,c,t] != 0
    __shared__ int    s_val[T_];            // caption values
    __shared__ int    s_eot;
    __shared__ float4 s_acc[2][C_][64];     // partial sums per T-half

    // ---- Stage packed noun_chunk_mask + caption values ----
    if (tid < T_) {
        int pack = 0;
        const int* mrow = noun_chunk_mask + (size_t)b * C_ * T_ + tid;
        #pragma unroll
        for (int c = 0; c < C_; ++c)
            if (mrow[c * T_] != 0) pack |= (1 << c);
        s_mask[tid] = pack;
        s_val[tid]  = captions[(size_t)b * T_ + tid];
    }

    // global_image slice = image_features[b, 0, h*256 : (h+1)*256] — T-half 1
    if (thalf) {
        const float4* img4 = reinterpret_cast<const float4*>(
            image_features + (size_t)b * LI_ * D_) + h * 64;
        float4 gi = img4[col];
        reinterpret_cast<float4*>(out + OFF_GI + (size_t)b * D_)[h * 64 + col] = gi;
    }
    __syncthreads();   // masks + caption vals staged

    // ---- Stream this T-half's rows of this D-half; accumulate 6 channels ----
    const int t0 = thalf ? T_SPLIT : 0;
    const int t1 = thalf ? T_      : T_SPLIT;

    const float4* trow = reinterpret_cast<const float4*>(
        text_features + (size_t)b * T_ * D_) + h * 64 + col;   // stride D/4

    float4 acc[C_];
    #pragma unroll
    for (int c = 0; c < C_; ++c) acc[c] = make_float4(0.f, 0.f, 0.f, 0.f);

    #pragma unroll 8
    for (int t = t0; t < t1; ++t) {
        float4 x = trow[t * (D_ / 4)];
        const int pack = s_mask[t];
        #pragma unroll
        for (int c = 0; c < C_; ++c) {
            if (pack & (1 << c)) {
                acc[c].x += x.x; acc[c].y += x.y;
                acc[c].z += x.z; acc[c].w += x.w;
            }
        }
    }

    // ---- Stash partials; warp 0 computes argmax concurrently ----
    #pragma unroll
    for (int c = 0; c < C_; ++c) s_acc[thalf][c][col] = acc[c];

    if (tid < 32) {
        int v = s_val[tid];
        int i = tid;
        #pragma unroll
        for (int k = 32; k < 96; k += 32) {
            int t = tid + k;
            if (t < T_) {
                int v2 = s_val[t];
                if (v2 > v) { v = v2; i = t; }   // strict > keeps first occurrence
            }
        }
        #pragma unroll
        for (int off = 16; off > 0; off >>= 1) {
            int v2 = __shfl_xor_sync(0xFFFFFFFFu, v, off);
            int i2 = __shfl_xor_sync(0xFFFFFFFFu, i, off);
            if (v2 > v || (v2 == v && i2 < i)) { v = v2; i = i2; }
        }
        if (tid == 0) s_eot = i;
    }
    __syncthreads();   // partials + eot ready

    // ---- Combine partials; each T-half finalizes 3 channels (this D-half) ----
    const float inv_T = 1.0f / (float)T_;
    float4* lt = reinterpret_cast<float4*>(out + OFF_LT + (size_t)b * C_ * D_)
                 + h * 64 + col;

    const int c0 = thalf * (C_ / 2);
    #pragma unroll
    for (int k = 0; k < C_ / 2; ++k) {
        const int c = c0 + k;
        float4 p0 = s_acc[0][c][col];
        float4 p1 = s_acc[1][c][col];
        float4 r;
        r.x = (p0.x + p1.x) * inv_T;
        r.y = (p0.y + p1.y) * inv_T;
        r.z = (p0.z + p1.z) * inv_T;
        r.w = (p0.w + p1.w) * inv_T;
        lt[c * (D_ / 4)] = r;
    }

    // global_text slice: gather eot row (resident in this SM's L1/L2)
    if (thalf == 0) {
        float4 g = trow[s_eot * (D_ / 4)];
        reinterpret_cast<float4*>(out + OFF_GT + (size_t)b * D_)[h * 64 + col] = g;
    }

    if (blockIdx.x == 0 && tid == 0) {
        out[OFF_LS] = logit_scale[0];
    }
}

extern "C" void kernel_launch(void* const* d_in, const int* in_sizes, int n_in,
                              void* d_out, int out_size)
{
    const float* image_features  = (const float*)d_in[0];
    const float* text_features   = (const float*)d_in[1];
    const float* logit_scale     = (const float*)d_in[2];
    const int*   captions        = (const int*)d_in[3];
    const int*   noun_chunk_mask = (const int*)d_in[4];
    float* out = (float*)d_out;

    clip_fused_kernel<<<B_ * 2, 128>>>(image_features, text_features, logit_scale,
                                       captions, noun_chunk_mask, out);
}